// round 13
// baseline (speedup 1.0000x reference)
#include <cuda_runtime.h>
#include <cuda_fp16.h>
#include <math.h>
#include <stdint.h>

// ---- problem constants ----
#define Nb   2
#define T    4096
#define Dd   1024
#define H    8
#define E    4
#define Lw   32
#define TC   128
#define DK   64
#define NT   (Nb*T)       // 8192
#define PC   1568         // 32 G + 512 K + 512 V + 512 Q
#define RLEN (Lw + T)     // 4128

#define TQ   32
#define WW   63
#define SST  260

#define STAGES 4
// one pipeline stage = 256 rows (128 A + 128 B) x 32 halves (64 B) = 16384 B
#define STAGE_BYTES 16384
#define STAGE_U32   4096

// ---- device scratch ----
__device__ __half  g_Wh[(size_t)PC*Dd];     // fp16 weights (concat)
__device__ float   g_bias[PC];
__device__ __half  g_Xh[(size_t)NT*Dd];     // fp16 X
__device__ float   g_P[(size_t)NT*PC];
__device__ float   g_recK[(size_t)Nb*E*RLEN*DK];
__device__ float   g_recV[(size_t)Nb*E*RLEN*DK];
__device__ __half  g_Yh[(size_t)NT*H*DK];   // fp16 attention output
__device__ __half  g_WoTh[(size_t)Dd*H*DK]; // fp16 w_O^T

// ============================================================
// helpers
// ============================================================
__device__ __forceinline__ void mma_f16(float4& c,
    uint32_t a0, uint32_t a1, uint32_t a2, uint32_t a3,
    uint32_t b0, uint32_t b1)
{
    asm volatile("mma.sync.aligned.m16n8k16.row.col.f32.f16.f16.f32 "
        "{%0,%1,%2,%3}, {%4,%5,%6,%7}, {%8,%9}, {%0,%1,%2,%3};"
        : "+f"(c.x), "+f"(c.y), "+f"(c.z), "+f"(c.w)
        : "r"(a0), "r"(a1), "r"(a2), "r"(a3), "r"(b0), "r"(b1));
}

__device__ __forceinline__ void cp16(uint32_t dst, const void* src, int sz) {
    asm volatile("cp.async.cg.shared.global [%0], [%1], 16, %2;"
                 :: "r"(dst), "l"(src), "r"(sz));
}
__device__ __forceinline__ void cp_commit() { asm volatile("cp.async.commit_group;"); }
__device__ __forceinline__ void cp_wait2()  { asm volatile("cp.async.wait_group 2;"); }

// packed fp32x2 math (sm_100+ base ISA) — exact fp32 semantics, 2 lanes/op
__device__ __forceinline__ uint64_t pack2(float lo, float hi) {
    uint64_t r;
    asm("mov.b64 %0, {%1, %2};" : "=l"(r)
        : "r"(__float_as_uint(lo)), "r"(__float_as_uint(hi)));
    return r;
}
__device__ __forceinline__ void unpack2(uint64_t v, float& lo, float& hi) {
    uint32_t a, b;
    asm("mov.b64 {%0, %1}, %2;" : "=r"(a), "=r"(b) : "l"(v));
    lo = __uint_as_float(a); hi = __uint_as_float(b);
}
__device__ __forceinline__ uint64_t ffma2(uint64_t a, uint64_t b, uint64_t c) {
    uint64_t d;
    asm("fma.rn.f32x2 %0, %1, %2, %3;" : "=l"(d) : "l"(a), "l"(b), "l"(c));
    return d;
}

// ============================================================
// FP16 GEMM (NT): unchanged (at the mma.sync path ceiling)
// ============================================================
template<bool ACT>
__global__ __launch_bounds__(128, 2) void mgemm(
    const __half* __restrict__ A, const __half* __restrict__ B,
    float* __restrict__ C, int M, int Nn, int K,
    const float* __restrict__ bias, int act_cols)
{
    extern __shared__ __align__(16) __half hsm[];

    int tid  = threadIdx.x;
    int bm   = blockIdx.y, bn = blockIdx.x;
    int warp = tid >> 5, lane = tid & 31;
    int wm   = (warp >> 1) * 64;
    int wn   = (warp & 1) * 64;
    int gid  = lane >> 2, tig = lane & 3;

    uint32_t sbase = (uint32_t)__cvta_generic_to_shared(hsm);

    const __half* srcp[8];
    uint32_t dsto[8];
    int szs[8];
    #pragma unroll
    for (int j = 0; j < 8; ++j) {
        int i = j*128 + tid;
        int row = i >> 2, c = i & 3;
        bool isA = row < 128;
        int g  = isA ? (bm*128 + row) : (bn*128 + (row - 128));
        int sz = isA ? 16 : ((g < Nn) ? 16 : 0);
        srcp[j] = (isA ? A + (size_t)g*K
                       : B + (size_t)(sz ? g : 0)*K) + c*8;
        dsto[j] = row*64 + c*16;
        szs[j]  = sz;
    }

    auto stage = [&](int kt, int s) {
        uint32_t d = sbase + s*STAGE_BYTES;
        #pragma unroll
        for (int j = 0; j < 8; ++j)
            cp16(d + dsto[j], srcp[j] + kt*32, szs[j]);
        cp_commit();
    };

    float4 acc[4][8];
    #pragma unroll
    for (int i = 0; i < 4; ++i)
        #pragma unroll
        for (int j = 0; j < 8; ++j) acc[i][j] = make_float4(0.f,0.f,0.f,0.f);

    int nk = K / 32;
    stage(0, 0);
    stage(1, 1);
    stage(2, 2);

    const uint32_t* Hs = (const uint32_t*)hsm;

    for (int kt0 = 0; kt0 < nk; kt0 += 4) {
        #pragma unroll
        for (int u = 0; u < 4; ++u) {
            int kt = kt0 + u;
            cp_wait2();
            __syncthreads();

            const uint32_t* as = Hs + u*STAGE_U32;
            const uint32_t* bs = as + 128*16;

            uint4 alo[4], ahi[4], bf[8];
            #pragma unroll
            for (int mf = 0; mf < 4; ++mf) {
                alo[mf] = *(const uint4*)&as[(wm + mf*16 + gid    )*16 + tig*4];
                ahi[mf] = *(const uint4*)&as[(wm + mf*16 + gid + 8)*16 + tig*4];
            }
            #pragma unroll
            for (int nf = 0; nf < 8; ++nf)
                bf[nf] = *(const uint4*)&bs[(wn + nf*8 + gid)*16 + tig*4];

            #pragma unroll
            for (int mf = 0; mf < 4; ++mf)
                #pragma unroll
                for (int nf = 0; nf < 8; ++nf) {
                    mma_f16(acc[mf][nf], alo[mf].x, ahi[mf].x, alo[mf].y, ahi[mf].y,
                                         bf[nf].x, bf[nf].y);
                    mma_f16(acc[mf][nf], alo[mf].z, ahi[mf].z, alo[mf].w, ahi[mf].w,
                                         bf[nf].z, bf[nf].w);
                }

            int kn = kt + 3;
            if (kn < nk) stage(kn, (u + 3) & 3);
            else cp_commit();
        }
    }

    #pragma unroll
    for (int mf = 0; mf < 4; ++mf) {
        int row = bm*128 + wm + mf*16 + gid;
        #pragma unroll
        for (int nf = 0; nf < 8; ++nf) {
            int col = bn*128 + wn + nf*8 + tig*2;
            if (col < Nn) {
                float4 v = acc[mf][nf];
                if (ACT && col < act_cols) {
                    v.x = 1.f/(1.f + __expf(-(v.x + bias[col])));
                    v.y = 1.f/(1.f + __expf(-(v.y + bias[col+1])));
                    v.z = 1.f/(1.f + __expf(-(v.z + bias[col])));
                    v.w = 1.f/(1.f + __expf(-(v.w + bias[col+1])));
                }
                *(float2*)(C + (size_t)row*Nn + col)     = make_float2(v.x, v.y);
                *(float2*)(C + (size_t)(row+8)*Nn + col) = make_float2(v.z, v.w);
            }
        }
    }
}

// ============================================================
// fused weight pack + fp16 convert
// ============================================================
__global__ void pack_weights(const float4* __restrict__ wG,
                             const float4* __restrict__ wK,
                             const float4* __restrict__ wV,
                             const float4* __restrict__ wQ)
{
    int i = blockIdx.x*blockDim.x + threadIdx.x;
    if (i >= PC*Dd/4) return;
    int row = i / (Dd/4);
    int c4  = i - row*(Dd/4);
    float4 v;
    if (row < 32)        v = wG[row*(Dd/4) + c4];
    else if (row < 544)  v = wK[(row-32)*(Dd/4) + c4];
    else if (row < 1056) v = wV[(row-544)*(Dd/4) + c4];
    else                 v = wQ[(row-1056)*(Dd/4) + c4];
    __half2* o = (__half2*)(g_Wh + (size_t)i*4);
    o[0] = __floats2half2_rn(v.x, v.y);
    o[1] = __floats2half2_rn(v.z, v.w);
}

__global__ void cvt_x(const float4* __restrict__ X, int n4)
{
    int i = blockIdx.x*blockDim.x + threadIdx.x;
    if (i < n4) {
        float4 v = X[i];
        __half2* o = (__half2*)(g_Xh + (size_t)i*4);
        o[0] = __floats2half2_rn(v.x, v.y);
        o[1] = __floats2half2_rn(v.z, v.w);
    }
}

// ============================================================
// FUSED gate + scan: block (n,e,l), 128 threads (64 K | 64 V).
// Per step t: a = 1-min(sum_h G,1); g = sum_h G * P[K/V col];
// st = a*st + g.  Arithmetic order identical to the old
// gate_combine + scan pair (sequential h, fmaf), so results match
// bitwise. 2-step software pipeline on the P-row loads.
// ============================================================
__global__ __launch_bounds__(128) void scan_fused(
    const float* __restrict__ initK, const float* __restrict__ initV)
{
    int b = blockIdx.x;
    int l = b % Lw, e = (b / Lw) % E, n = b / (Lw*E);
    int tid = threadIdx.x;
    bool isV = tid >= 64;
    int d = tid & 63;
    const float* init = isV ? initV : initK;
    float*       rec  = isV ? g_recV : g_recK;
    int off = isV ? 544 : 32;

    size_t base = (size_t)(n*E + e);
    int t0 = l*TC;

    float st = init[(e*Lw + l)*DK + d];
    rec[(base*RLEN + l)*DK + d] = st;
    float* recrow = rec + (base*RLEN + Lw + t0)*(size_t)DK + d;

    const float* Pb = g_P + ((size_t)(n*T + t0))*PC;

    float GA[8], XA[8], GB[8], XB[8];
    #pragma unroll
    for (int h = 0; h < 8; ++h) {
        GA[h] = Pb[h*E + e];
        XA[h] = Pb[off + h*64 + d];
    }
    {
        const float* Pr = Pb + PC;
        #pragma unroll
        for (int h = 0; h < 8; ++h) {
            GB[h] = Pr[h*E + e];
            XB[h] = Pr[off + h*64 + d];
        }
    }

    for (int c0 = 0; c0 < TC; c0 += 2) {
        float nGA[8], nXA[8], nGB[8], nXB[8];
        bool more = (c0 + 2 < TC);
        if (more) {
            const float* Pr = Pb + (size_t)(c0+2)*PC;
            #pragma unroll
            for (int h = 0; h < 8; ++h) {
                nGA[h] = Pr[h*E + e];
                nXA[h] = Pr[off + h*64 + d];
            }
        }
        // step t = c0
        {
            float asum = 0.f, g = 0.f;
            #pragma unroll
            for (int h = 0; h < 8; ++h) {
                asum += GA[h];
                g = fmaf(GA[h], XA[h], g);
            }
            float a = 1.f - fminf(asum, 1.f);
            st = fmaf(a, st, g);
            recrow[(size_t)c0*DK] = st;
        }
        if (more) {
            const float* Pr = Pb + (size_t)(c0+3)*PC;
            #pragma unroll
            for (int h = 0; h < 8; ++h) {
                nGB[h] = Pr[h*E + e];
                nXB[h] = Pr[off + h*64 + d];
            }
        }
        // step t = c0+1
        {
            float asum = 0.f, g = 0.f;
            #pragma unroll
            for (int h = 0; h < 8; ++h) {
                asum += GB[h];
                g = fmaf(GB[h], XB[h], g);
            }
            float a = 1.f - fminf(asum, 1.f);
            st = fmaf(a, st, g);
            recrow[(size_t)(c0+1)*DK] = st;
        }
        #pragma unroll
        for (int h = 0; h < 8; ++h) {
            GA[h] = nGA[h]; XA[h] = nXA[h];
            GB[h] = nGB[h]; XB[h] = nXB[h];
        }
    }
}

// ============================================================
// Attention: branch-free softmax (norm-bound shift), packed f32x2
// ============================================================
extern __shared__ float sm_att[];

__global__ __launch_bounds__(256, 1) void attention_kernel()
{
    float* Ks = sm_att;
    float* Vs = sm_att + WW*SST;
    __shared__ int s_maxk;
    int bid = blockIdx.x;
    int n    = bid / (T/TQ);
    int tile = bid % (T/TQ);
    int t0 = tile*TQ;
    int tid = threadIdx.x;

    if (tid == 0) s_maxk = 0;

    for (int i = tid; i < WW*E*16; i += 256) {
        int w   = i >> 6;
        int rem = i & 63;
        int e = rem >> 4, d4 = rem & 15;
        size_t go = (((size_t)(n*E + e))*RLEN + (1 + t0 + w))*DK + d4*4;
        float4 kv = *(const float4*)(g_recK + go);
        float4 vv = *(const float4*)(g_recV + go);
        int so = w*SST + e*64 + d4*4;
        *(float4*)(Ks + so) = kv;
        *(float4*)(Vs + so) = vv;
    }
    __syncthreads();

    if (tid < WW*E) {
        int w = tid >> 2, e = tid & 3;
        const float4* kp = (const float4*)(Ks + w*SST + e*64);
        float ss = 0.f;
        #pragma unroll
        for (int i = 0; i < 16; ++i) {
            float4 k4 = kp[i];
            ss = fmaf(k4.x,k4.x, fmaf(k4.y,k4.y, fmaf(k4.z,k4.z, fmaf(k4.w,k4.w, ss))));
        }
        atomicMax(&s_maxk, __float_as_int(ss));
    }

    int h = tid & 7, tq = tid >> 3;
    int t = t0 + tq;

    uint64_t q2[32];
    float qss = 0.f;
    const ulonglong2* Qp2 = (const ulonglong2*)(g_P + (size_t)(n*T + t)*PC + 1056 + h*64);
    #pragma unroll
    for (int i = 0; i < 16; ++i) {
        ulonglong2 v = Qp2[i];
        q2[2*i]   = v.x;
        q2[2*i+1] = v.y;
        float a,b,c,d;
        unpack2(v.x, a, b); unpack2(v.y, c, d);
        qss = fmaf(a,a, fmaf(b,b, fmaf(c,c, fmaf(d,d, qss))));
    }
    __syncthreads();

    float m = 0.125f * sqrtf(qss) * sqrtf(__int_as_float(s_maxk));

    float sum = 0.f;
    uint64_t acc2[32];
    #pragma unroll
    for (int i = 0; i < 32; ++i) acc2[i] = 0ull;

    for (int e = 0; e < E; ++e) {
        for (int l = 0; l < Lw; ++l) {
            int base = (tq + l)*SST + e*64;
            const ulonglong2* kp2 = (const ulonglong2*)(Ks + base);
            uint64_t sa = 0ull, sb = 0ull, sc = 0ull, sd = 0ull;
            #pragma unroll
            for (int i = 0; i < 8; ++i) {
                ulonglong2 k0 = kp2[2*i];
                ulonglong2 k1 = kp2[2*i+1];
                sa = ffma2(q2[4*i],   k0.x, sa);
                sb = ffma2(q2[4*i+1], k0.y, sb);
                sc = ffma2(q2[4*i+2], k1.x, sc);
                sd = ffma2(q2[4*i+3], k1.y, sd);
            }
            float a0, a1, b0, b1, c0, c1, d0, d1;
            unpack2(sa, a0, a1); unpack2(sb, b0, b1);
            unpack2(sc, c0, c1); unpack2(sd, d0, d1);
            float s = (((a0 + a1) + (b0 + b1)) + ((c0 + c1) + (d0 + d1))) * 0.125f;

            float p = __expf(fmaxf(s - m, -75.f));
            sum += p;
            uint64_t p2 = pack2(p, p);
            const ulonglong2* vp2 = (const ulonglong2*)(Vs + base);
            #pragma unroll
            for (int i = 0; i < 16; ++i) {
                ulonglong2 v = vp2[i];
                acc2[2*i]   = ffma2(p2, v.x, acc2[2*i]);
                acc2[2*i+1] = ffma2(p2, v.y, acc2[2*i+1]);
            }
        }
    }

    float inv = 1.f / sum;
    __half2* Yp = (__half2*)(g_Yh + (size_t)(n*T + t)*(H*DK) + h*64);
    #pragma unroll
    for (int i = 0; i < 32; ++i) {
        float lo, hi;
        unpack2(acc2[i], lo, hi);
        Yp[i] = __floats2half2_rn(lo*inv, hi*inv);
    }
}

// ============================================================
// w_O transpose: (512,1024) -> (1024,512), fp16 output
// ============================================================
__global__ void transpose_wo(const float* __restrict__ src)
{
    __shared__ float tile[32][33];
    int tx = threadIdx.x, ty = threadIdx.y;
    int x = blockIdx.x*32 + tx;
    int y = blockIdx.y*32 + ty;
    #pragma unroll
    for (int i = 0; i < 32; i += 8)
        tile[ty+i][tx] = src[(size_t)(y+i)*Dd + x];
    __syncthreads();
    int x2 = blockIdx.y*32 + tx;
    int y2 = blockIdx.x*32 + ty;
    #pragma unroll
    for (int i = 0; i < 32; i += 8)
        g_WoTh[(size_t)(y2+i)*(H*DK) + x2] = __float2half_rn(tile[tx][ty+i]);
}

// ============================================================
extern "C" void kernel_launch(void* const* d_in, const int* in_sizes, int n_in,
                              void* d_out, int out_size)
{
    const float* X  = (const float*)d_in[0];
    const float* wG = (const float*)d_in[1];
    const float* bG = (const float*)d_in[2];
    const float* wK = (const float*)d_in[3];
    const float* wV = (const float*)d_in[4];
    const float* wQ = (const float*)d_in[5];
    const float* wO = (const float*)d_in[6];
    const float* iK = (const float*)d_in[7];
    const float* iV = (const float*)d_in[8];
    float* out = (float*)d_out;

    cudaMemcpyToSymbolAsync(g_bias, bG, 32*sizeof(float), 0, cudaMemcpyDeviceToDevice, 0);

    float *dBias, *dP;
    __half *dXh, *dWh, *dYh, *dWoTh;
    cudaGetSymbolAddress((void**)&dWh,   g_Wh);
    cudaGetSymbolAddress((void**)&dBias, g_bias);
    cudaGetSymbolAddress((void**)&dP,    g_P);
    cudaGetSymbolAddress((void**)&dYh,   g_Yh);
    cudaGetSymbolAddress((void**)&dWoTh, g_WoTh);
    cudaGetSymbolAddress((void**)&dXh,   g_Xh);

    // pack + convert operands to fp16
    pack_weights<<<(PC*Dd/4 + 255)/256, 256>>>(
        (const float4*)wG, (const float4*)wK, (const float4*)wV, (const float4*)wQ);
    cvt_x<<<((NT*Dd/4) + 255)/256, 256>>>((const float4*)X, NT*Dd/4);
    transpose_wo<<<dim3(Dd/32, (H*DK)/32), dim3(32,8)>>>(wO);

    int gsmem = STAGES*STAGE_BYTES;   // 65536 B
    cudaFuncSetAttribute(mgemm<true>,  cudaFuncAttributeMaxDynamicSharedMemorySize, gsmem);
    cudaFuncSetAttribute(mgemm<false>, cudaFuncAttributeMaxDynamicSharedMemorySize, gsmem);

    // 1) fused projection GEMM (fp16 tensor cores, fp32 accum)
    mgemm<true><<<dim3((PC+127)/128, NT/128), 128, gsmem>>>(
        dXh, dWh, dP, NT, PC, Dd, dBias, 32);

    // 2) fused gate + scan
    scan_fused<<<Nb*E*Lw, 128>>>(iK, iV);

    // 3) attention (branch-free softmax, packed f32x2)
    int smem_bytes = 2*WW*SST*sizeof(float);
    cudaFuncSetAttribute(attention_kernel, cudaFuncAttributeMaxDynamicSharedMemorySize, smem_bytes);
    attention_kernel<<<Nb*(T/TQ), 256, smem_bytes>>>();

    // 4) output projection
    mgemm<false><<<dim3(Dd/128, NT/128), 128, gsmem>>>(
        dYh, dWoTh, out, NT, Dd, H*DK, nullptr, 0);
}

// round 14
// speedup vs baseline: 1.1173x; 1.1173x over previous
#include <cuda_runtime.h>
#include <cuda_fp16.h>
#include <math.h>
#include <stdint.h>

// ---- problem constants ----
#define Nb   2
#define T    4096
#define Dd   1024
#define H    8
#define E    4
#define Lw   32
#define TC   128
#define DK   64
#define NT   (Nb*T)       // 8192
#define PC   1568         // 32 G + 512 K + 512 V + 512 Q
#define RLEN (Lw + T)     // 4128

#define TQ   32
#define WW   63
#define SST  260

#define STAGES 4
#define STAGE_BYTES 16384
#define STAGE_U32   4096

// ---- device scratch ----
__device__ __half  g_Wh[(size_t)PC*Dd];     // fp16 weights (concat)
__device__ float   g_bias[PC];
__device__ __half  g_Xh[(size_t)NT*Dd];     // fp16 X
__device__ float   g_P[(size_t)NT*PC];
__device__ float   g_A[Nb*E*T];
__device__ float   g_gK[(size_t)Nb*E*T*DK];
__device__ float   g_gV[(size_t)Nb*E*T*DK];
__device__ float   g_recK[(size_t)Nb*E*RLEN*DK];
__device__ float   g_recV[(size_t)Nb*E*RLEN*DK];
__device__ __half  g_Yh[(size_t)NT*H*DK];   // fp16 attention output
__device__ __half  g_WoTh[(size_t)Dd*H*DK]; // fp16 w_O^T

// ============================================================
// helpers
// ============================================================
__device__ __forceinline__ void mma_f16(float4& c,
    uint32_t a0, uint32_t a1, uint32_t a2, uint32_t a3,
    uint32_t b0, uint32_t b1)
{
    asm volatile("mma.sync.aligned.m16n8k16.row.col.f32.f16.f16.f32 "
        "{%0,%1,%2,%3}, {%4,%5,%6,%7}, {%8,%9}, {%0,%1,%2,%3};"
        : "+f"(c.x), "+f"(c.y), "+f"(c.z), "+f"(c.w)
        : "r"(a0), "r"(a1), "r"(a2), "r"(a3), "r"(b0), "r"(b1));
}

__device__ __forceinline__ void cp16(uint32_t dst, const void* src, int sz) {
    asm volatile("cp.async.cg.shared.global [%0], [%1], 16, %2;"
                 :: "r"(dst), "l"(src), "r"(sz));
}
__device__ __forceinline__ void cp_commit() { asm volatile("cp.async.commit_group;"); }
__device__ __forceinline__ void cp_wait2()  { asm volatile("cp.async.wait_group 2;"); }

// packed fp32x2 math — exact fp32 semantics, 2 lanes/op
__device__ __forceinline__ uint64_t pack2(float lo, float hi) {
    uint64_t r;
    asm("mov.b64 %0, {%1, %2};" : "=l"(r)
        : "r"(__float_as_uint(lo)), "r"(__float_as_uint(hi)));
    return r;
}
__device__ __forceinline__ void unpack2(uint64_t v, float& lo, float& hi) {
    uint32_t a, b;
    asm("mov.b64 {%0, %1}, %2;" : "=r"(a), "=r"(b) : "l"(v));
    lo = __uint_as_float(a); hi = __uint_as_float(b);
}
__device__ __forceinline__ uint64_t ffma2(uint64_t a, uint64_t b, uint64_t c) {
    uint64_t d;
    asm("fma.rn.f32x2 %0, %1, %2, %3;" : "=l"(d) : "l"(a), "l"(b), "l"(c));
    return d;
}

// ============================================================
// FP16 GEMM (NT) with ldc: C[row*ldc + col] = A[M][K] * B[Nn][K]^T
// BM=128, BN=128, BK=32. 128 threads, 4 warps of 64x64, 4-stage
// cp.async pipeline (unrolled x4), 2 CTAs/SM.
// ============================================================
template<bool ACT>
__global__ __launch_bounds__(128, 2) void mgemm(
    const __half* __restrict__ A, const __half* __restrict__ B,
    float* __restrict__ C, int M, int Nn, int K, int ldc,
    const float* __restrict__ bias, int act_cols)
{
    extern __shared__ __align__(16) __half hsm[];

    int tid  = threadIdx.x;
    int bm   = blockIdx.y, bn = blockIdx.x;
    int warp = tid >> 5, lane = tid & 31;
    int wm   = (warp >> 1) * 64;
    int wn   = (warp & 1) * 64;
    int gid  = lane >> 2, tig = lane & 3;

    uint32_t sbase = (uint32_t)__cvta_generic_to_shared(hsm);

    const __half* srcp[8];
    uint32_t dsto[8];
    int szs[8];
    #pragma unroll
    for (int j = 0; j < 8; ++j) {
        int i = j*128 + tid;
        int row = i >> 2, c = i & 3;
        bool isA = row < 128;
        int g  = isA ? (bm*128 + row) : (bn*128 + (row - 128));
        int sz = isA ? 16 : ((g < Nn) ? 16 : 0);
        srcp[j] = (isA ? A + (size_t)g*K
                       : B + (size_t)(sz ? g : 0)*K) + c*8;
        dsto[j] = row*64 + c*16;
        szs[j]  = sz;
    }

    auto stage = [&](int kt, int s) {
        uint32_t d = sbase + s*STAGE_BYTES;
        #pragma unroll
        for (int j = 0; j < 8; ++j)
            cp16(d + dsto[j], srcp[j] + kt*32, szs[j]);
        cp_commit();
    };

    float4 acc[4][8];
    #pragma unroll
    for (int i = 0; i < 4; ++i)
        #pragma unroll
        for (int j = 0; j < 8; ++j) acc[i][j] = make_float4(0.f,0.f,0.f,0.f);

    int nk = K / 32;
    stage(0, 0);
    stage(1, 1);
    stage(2, 2);

    const uint32_t* Hs = (const uint32_t*)hsm;

    for (int kt0 = 0; kt0 < nk; kt0 += 4) {
        #pragma unroll
        for (int u = 0; u < 4; ++u) {
            int kt = kt0 + u;
            cp_wait2();
            __syncthreads();

            const uint32_t* as = Hs + u*STAGE_U32;
            const uint32_t* bs = as + 128*16;

            uint4 alo[4], ahi[4], bf[8];
            #pragma unroll
            for (int mf = 0; mf < 4; ++mf) {
                alo[mf] = *(const uint4*)&as[(wm + mf*16 + gid    )*16 + tig*4];
                ahi[mf] = *(const uint4*)&as[(wm + mf*16 + gid + 8)*16 + tig*4];
            }
            #pragma unroll
            for (int nf = 0; nf < 8; ++nf)
                bf[nf] = *(const uint4*)&bs[(wn + nf*8 + gid)*16 + tig*4];

            #pragma unroll
            for (int mf = 0; mf < 4; ++mf)
                #pragma unroll
                for (int nf = 0; nf < 8; ++nf) {
                    mma_f16(acc[mf][nf], alo[mf].x, ahi[mf].x, alo[mf].y, ahi[mf].y,
                                         bf[nf].x, bf[nf].y);
                    mma_f16(acc[mf][nf], alo[mf].z, ahi[mf].z, alo[mf].w, ahi[mf].w,
                                         bf[nf].z, bf[nf].w);
                }

            int kn = kt + 3;
            if (kn < nk) stage(kn, (u + 3) & 3);
            else cp_commit();
        }
    }

    #pragma unroll
    for (int mf = 0; mf < 4; ++mf) {
        int row = bm*128 + wm + mf*16 + gid;
        #pragma unroll
        for (int nf = 0; nf < 8; ++nf) {
            int col = bn*128 + wn + nf*8 + tig*2;
            if (col < Nn) {
                float4 v = acc[mf][nf];
                if (ACT && col < act_cols) {
                    v.x = 1.f/(1.f + __expf(-(v.x + bias[col])));
                    v.y = 1.f/(1.f + __expf(-(v.y + bias[col+1])));
                    v.z = 1.f/(1.f + __expf(-(v.z + bias[col])));
                    v.w = 1.f/(1.f + __expf(-(v.w + bias[col+1])));
                }
                *(float2*)(C + (size_t)row*ldc + col)     = make_float2(v.x, v.y);
                *(float2*)(C + (size_t)(row+8)*ldc + col) = make_float2(v.z, v.w);
            }
        }
    }
}

// ============================================================
// fused weight pack + fp16 convert
// ============================================================
__global__ void pack_weights(const float4* __restrict__ wG,
                             const float4* __restrict__ wK,
                             const float4* __restrict__ wV,
                             const float4* __restrict__ wQ)
{
    int i = blockIdx.x*blockDim.x + threadIdx.x;
    if (i >= PC*Dd/4) return;
    int row = i / (Dd/4);
    int c4  = i - row*(Dd/4);
    float4 v;
    if (row < 32)        v = wG[row*(Dd/4) + c4];
    else if (row < 544)  v = wK[(row-32)*(Dd/4) + c4];
    else if (row < 1056) v = wV[(row-544)*(Dd/4) + c4];
    else                 v = wQ[(row-1056)*(Dd/4) + c4];
    __half2* o = (__half2*)(g_Wh + (size_t)i*4);
    o[0] = __floats2half2_rn(v.x, v.y);
    o[1] = __floats2half2_rn(v.z, v.w);
}

__global__ void cvt_x(const float4* __restrict__ X, int n4)
{
    int i = blockIdx.x*blockDim.x + threadIdx.x;
    if (i < n4) {
        float4 v = X[i];
        __half2* o = (__half2*)(g_Xh + (size_t)i*4);
        o[0] = __floats2half2_rn(v.x, v.y);
        o[1] = __floats2half2_rn(v.z, v.w);
    }
}

// ============================================================
// Gate combine (round-12 version)
// ============================================================
__global__ __launch_bounds__(256) void gate_combine()
{
    int row = blockIdx.x;
    int n = row / T, t = row - n*T;
    __shared__ float sG[H*E];
    int tid = threadIdx.x;
    const float* Pr = g_P + (size_t)row*PC;
    if (tid < H*E) sG[tid] = Pr[tid];
    __syncthreads();
    if (tid < E) {
        float s = 0.f;
        #pragma unroll
        for (int h = 0; h < H; ++h) s += sG[h*E + tid];
        g_A[(n*E + tid)*T + t] = 1.f - fminf(s, 1.f);
    }
    int e = tid >> 6, d = tid & 63;
    float sk = 0.f, sv = 0.f;
    #pragma unroll
    for (int h = 0; h < H; ++h) {
        float g = sG[h*E + e];
        sk = fmaf(g, Pr[32  + h*64 + d], sk);
        sv = fmaf(g, Pr[544 + h*64 + d], sv);
    }
    size_t o = ((size_t)(n*E + e)*T + t)*DK + d;
    g_gK[o] = sk;
    g_gV[o] = sv;
}

// ============================================================
// Scan (round-12 version: prefetch distance 16)
// ============================================================
__global__ __launch_bounds__(128) void scan_kernel(
    const float* __restrict__ initK, const float* __restrict__ initV)
{
    __shared__ float sa[TC];
    int b = blockIdx.x;
    int l = b % Lw, e = (b / Lw) % E, n = b / (Lw*E);
    int tid = threadIdx.x;
    bool isV = tid >= 64;
    int d = tid & 63;
    const float* init = isV ? initV : initK;
    const float* g    = isV ? g_gV  : g_gK;
    float*       rec  = isV ? g_recV : g_recK;

    size_t base = (size_t)(n*E + e);
    int t0 = l*TC;
    const float* Arow = g_A + base*T + t0;
    if (tid < TC) sa[tid] = Arow[tid];
    __syncthreads();

    float st = init[(e*Lw + l)*DK + d];
    rec[(base*RLEN + l)*DK + d] = st;
    const float* grow   = g   + (base*T   + t0)*(size_t)DK + d;
    float*       recrow = rec + (base*RLEN + Lw + t0)*(size_t)DK + d;

    float bufA[8], bufB[8];
    #pragma unroll
    for (int j = 0; j < 8; ++j) bufA[j] = grow[(size_t)j*DK];
    #pragma unroll
    for (int j = 0; j < 8; ++j) bufB[j] = grow[(size_t)(8+j)*DK];

    for (int c0 = 0; c0 < TC; c0 += 16) {
        float nA[8], nB[8];
        bool more = (c0 + 16 < TC);
        if (more) {
            #pragma unroll
            for (int j = 0; j < 8; ++j) nA[j] = grow[(size_t)(c0+16+j)*DK];
        }
        #pragma unroll
        for (int j = 0; j < 8; ++j) {
            st = fmaf(sa[c0+j], st, bufA[j]);
            recrow[(size_t)(c0+j)*DK] = st;
        }
        if (more) {
            #pragma unroll
            for (int j = 0; j < 8; ++j) nB[j] = grow[(size_t)(c0+24+j)*DK];
        }
        #pragma unroll
        for (int j = 0; j < 8; ++j) {
            st = fmaf(sa[c0+8+j], st, bufB[j]);
            recrow[(size_t)(c0+8+j)*DK] = st;
        }
        #pragma unroll
        for (int j = 0; j < 8; ++j) { bufA[j] = nA[j]; bufB[j] = nB[j]; }
    }
}

// ============================================================
// Attention: branch-free softmax (norm-bound shift), packed f32x2
// ============================================================
extern __shared__ float sm_att[];

__global__ __launch_bounds__(256, 1) void attention_kernel()
{
    float* Ks = sm_att;
    float* Vs = sm_att + WW*SST;
    __shared__ int s_maxk;
    int bid = blockIdx.x;
    int n    = bid / (T/TQ);
    int tile = bid % (T/TQ);
    int t0 = tile*TQ;
    int tid = threadIdx.x;

    if (tid == 0) s_maxk = 0;

    for (int i = tid; i < WW*E*16; i += 256) {
        int w   = i >> 6;
        int rem = i & 63;
        int e = rem >> 4, d4 = rem & 15;
        size_t go = (((size_t)(n*E + e))*RLEN + (1 + t0 + w))*DK + d4*4;
        float4 kv = *(const float4*)(g_recK + go);
        float4 vv = *(const float4*)(g_recV + go);
        int so = w*SST + e*64 + d4*4;
        *(float4*)(Ks + so) = kv;
        *(float4*)(Vs + so) = vv;
    }
    __syncthreads();

    if (tid < WW*E) {
        int w = tid >> 2, e = tid & 3;
        const float4* kp = (const float4*)(Ks + w*SST + e*64);
        float ss = 0.f;
        #pragma unroll
        for (int i = 0; i < 16; ++i) {
            float4 k4 = kp[i];
            ss = fmaf(k4.x,k4.x, fmaf(k4.y,k4.y, fmaf(k4.z,k4.z, fmaf(k4.w,k4.w, ss))));
        }
        atomicMax(&s_maxk, __float_as_int(ss));
    }

    int h = tid & 7, tq = tid >> 3;
    int t = t0 + tq;

    uint64_t q2[32];
    float qss = 0.f;
    const ulonglong2* Qp2 = (const ulonglong2*)(g_P + (size_t)(n*T + t)*PC + 1056 + h*64);
    #pragma unroll
    for (int i = 0; i < 16; ++i) {
        ulonglong2 v = Qp2[i];
        q2[2*i]   = v.x;
        q2[2*i+1] = v.y;
        float a,b,c,d;
        unpack2(v.x, a, b); unpack2(v.y, c, d);
        qss = fmaf(a,a, fmaf(b,b, fmaf(c,c, fmaf(d,d, qss))));
    }
    __syncthreads();

    float m = 0.125f * sqrtf(qss) * sqrtf(__int_as_float(s_maxk));

    float sum = 0.f;
    uint64_t acc2[32];
    #pragma unroll
    for (int i = 0; i < 32; ++i) acc2[i] = 0ull;

    for (int e = 0; e < E; ++e) {
        for (int l = 0; l < Lw; ++l) {
            int base = (tq + l)*SST + e*64;
            const ulonglong2* kp2 = (const ulonglong2*)(Ks + base);
            uint64_t sa = 0ull, sb = 0ull, sc = 0ull, sd = 0ull;
            #pragma unroll
            for (int i = 0; i < 8; ++i) {
                ulonglong2 k0 = kp2[2*i];
                ulonglong2 k1 = kp2[2*i+1];
                sa = ffma2(q2[4*i],   k0.x, sa);
                sb = ffma2(q2[4*i+1], k0.y, sb);
                sc = ffma2(q2[4*i+2], k1.x, sc);
                sd = ffma2(q2[4*i+3], k1.y, sd);
            }
            float a0, a1, b0, b1, c0, c1, d0, d1;
            unpack2(sa, a0, a1); unpack2(sb, b0, b1);
            unpack2(sc, c0, c1); unpack2(sd, d0, d1);
            float s = (((a0 + a1) + (b0 + b1)) + ((c0 + c1) + (d0 + d1))) * 0.125f;

            float p = __expf(fmaxf(s - m, -75.f));
            sum += p;
            uint64_t p2 = pack2(p, p);
            const ulonglong2* vp2 = (const ulonglong2*)(Vs + base);
            #pragma unroll
            for (int i = 0; i < 16; ++i) {
                ulonglong2 v = vp2[i];
                acc2[2*i]   = ffma2(p2, v.x, acc2[2*i]);
                acc2[2*i+1] = ffma2(p2, v.y, acc2[2*i+1]);
            }
        }
    }

    float inv = 1.f / sum;
    __half2* Yp = (__half2*)(g_Yh + (size_t)(n*T + t)*(H*DK) + h*64);
    #pragma unroll
    for (int i = 0; i < 32; ++i) {
        float lo, hi;
        unpack2(acc2[i], lo, hi);
        Yp[i] = __floats2half2_rn(lo*inv, hi*inv);
    }
}

// ============================================================
// w_O transpose: (512,1024) -> (1024,512), fp16 output
// ============================================================
__global__ void transpose_wo(const float* __restrict__ src)
{
    __shared__ float tile[32][33];
    int tx = threadIdx.x, ty = threadIdx.y;
    int x = blockIdx.x*32 + tx;
    int y = blockIdx.y*32 + ty;
    #pragma unroll
    for (int i = 0; i < 32; i += 8)
        tile[ty+i][tx] = src[(size_t)(y+i)*Dd + x];
    __syncthreads();
    int x2 = blockIdx.y*32 + tx;
    int y2 = blockIdx.x*32 + ty;
    #pragma unroll
    for (int i = 0; i < 32; i += 8)
        g_WoTh[(size_t)(y2+i)*(H*DK) + x2] = __float2half_rn(tile[tx][ty+i]);
}

// ============================================================
extern "C" void kernel_launch(void* const* d_in, const int* in_sizes, int n_in,
                              void* d_out, int out_size)
{
    const float* X  = (const float*)d_in[0];
    const float* wG = (const float*)d_in[1];
    const float* bG = (const float*)d_in[2];
    const float* wK = (const float*)d_in[3];
    const float* wV = (const float*)d_in[4];
    const float* wQ = (const float*)d_in[5];
    const float* wO = (const float*)d_in[6];
    const float* iK = (const float*)d_in[7];
    const float* iV = (const float*)d_in[8];
    float* out = (float*)d_out;

    cudaMemcpyToSymbolAsync(g_bias, bG, 32*sizeof(float), 0, cudaMemcpyDeviceToDevice, 0);

    float *dBias, *dP;
    __half *dXh, *dWh, *dYh, *dWoTh;
    cudaGetSymbolAddress((void**)&dWh,   g_Wh);
    cudaGetSymbolAddress((void**)&dBias, g_bias);
    cudaGetSymbolAddress((void**)&dP,    g_P);
    cudaGetSymbolAddress((void**)&dYh,   g_Yh);
    cudaGetSymbolAddress((void**)&dWoTh, g_WoTh);
    cudaGetSymbolAddress((void**)&dXh,   g_Xh);

    // side stream (non-blocking: no legacy-stream implicit sync)
    cudaStream_t s2;
    cudaStreamCreateWithFlags(&s2, cudaStreamNonBlocking);
    cudaEvent_t e1, e3;
    cudaEventCreateWithFlags(&e1, cudaEventDisableTiming);
    cudaEventCreateWithFlags(&e3, cudaEventDisableTiming);

    // prep (main stream)
    pack_weights<<<(PC*Dd/4 + 255)/256, 256>>>(
        (const float4*)wG, (const float4*)wK, (const float4*)wV, (const float4*)wQ);
    cvt_x<<<((NT*Dd/4) + 255)/256, 256>>>((const float4*)X, NT*Dd/4);

    int gsmem = STAGES*STAGE_BYTES;   // 65536 B
    cudaFuncSetAttribute(mgemm<true>,  cudaFuncAttributeMaxDynamicSharedMemorySize, gsmem);
    cudaFuncSetAttribute(mgemm<false>, cudaFuncAttributeMaxDynamicSharedMemorySize, gsmem);

    // 1a) projection GEMM, cols 0..1055 (G,K,V) + sigmoid epilogue
    mgemm<true><<<dim3(9, NT/128), 128, gsmem>>>(
        dXh, dWh, dP, NT, 1056, Dd, PC, dBias, 32);
    cudaEventRecord(e1, 0);

    // side stream: transpose_wo + Q-column GEMM, overlapping gate/scan
    cudaStreamWaitEvent(s2, e1, 0);
    transpose_wo<<<dim3(Dd/32, (H*DK)/32), dim3(32,8), 0, s2>>>(wO);
    mgemm<false><<<dim3(4, NT/128), 128, gsmem, s2>>>(
        dXh, dWh + (size_t)1056*Dd, dP + 1056, NT, 512, Dd, PC, nullptr, 0);
    cudaEventRecord(e3, s2);

    // main stream: gates + scans (need only G,K,V columns)
    gate_combine<<<NT, 256>>>();
    scan_kernel<<<Nb*E*Lw, 128>>>(iK, iV);

    // join: attention needs Q columns too
    cudaStreamWaitEvent(0, e3, 0);

    int smem_bytes = 2*WW*SST*sizeof(float);
    cudaFuncSetAttribute(attention_kernel, cudaFuncAttributeMaxDynamicSharedMemorySize, smem_bytes);
    attention_kernel<<<Nb*(T/TQ), 256, smem_bytes>>>();

    // output projection
    mgemm<false><<<dim3(Dd/128, NT/128), 128, gsmem>>>(
        dYh, dWoTh, out, NT, Dd, H*DK, Dd, nullptr, 0);

    cudaEventDestroy(e1);
    cudaEventDestroy(e3);
    cudaStreamDestroy(s2);
}